// round 12
// baseline (speedup 1.0000x reference)
#include <cuda_runtime.h>
#include <cuda_fp16.h>
#include <cstdint>
#include <cstddef>

#define Bv     8
#define Nv     128
#define FNv    64

// ------------------------------ helpers ------------------------------
__device__ __forceinline__ uint32_t smem_u32(const void* p) {
    uint32_t a;
    asm("{ .reg .u64 t; cvta.to.shared.u64 t, %1; cvt.u32.u64 %0, t; }" : "=r"(a) : "l"(p));
    return a;
}
__device__ __forceinline__ void cp16(uint32_t dst, const void* src) {
    asm volatile("cp.async.cg.shared.global [%0], [%1], 16;" :: "r"(dst), "l"(src) : "memory");
}
__device__ __forceinline__ void cp_commit() {
    asm volatile("cp.async.commit_group;" ::: "memory");
}
template <int N>
__device__ __forceinline__ void cp_wait() {
    asm volatile("cp.async.wait_group %0;" :: "n"(N) : "memory");
}
__device__ __forceinline__ uint32_t packh2(float lo, float hi) {
    uint32_t d; asm("cvt.rn.f16x2.f32 %0, %1, %2;" : "=r"(d) : "f"(hi), "f"(lo)); return d;
}
__device__ __forceinline__ void mma16(float* c, const uint32_t* a, uint32_t b0, uint32_t b1) {
    asm volatile(
        "mma.sync.aligned.m16n8k16.row.col.f32.f16.f16.f32 "
        "{%0,%1,%2,%3}, {%4,%5,%6,%7}, {%8,%9}, {%0,%1,%2,%3};"
        : "+f"(c[0]), "+f"(c[1]), "+f"(c[2]), "+f"(c[3])
        : "r"(a[0]), "r"(a[1]), "r"(a[2]), "r"(a[3]), "r"(b0), "r"(b1));
}
__device__ __forceinline__ double pack2d(float x, float y) {
    double r; asm("mov.b64 %0, {%1, %2};" : "=d"(r) : "f"(x), "f"(y)); return r;
}
__device__ __forceinline__ double add2(double a, double b) {
    double r; asm("add.rn.f32x2 %0, %1, %2;" : "=d"(r) : "d"(a), "d"(b)); return r;
}
__device__ __forceinline__ double fma2v(double a, double b, double c) {
    double r; asm("fma.rn.f32x2 %0, %1, %2, %3;" : "=d"(r) : "d"(a), "d"(b), "d"(c)); return r;
}
__device__ __forceinline__ float2 unpack2d(double v) {
    float2 f; asm("mov.b64 {%0, %1}, %2;" : "=f"(f.x), "=f"(f.y) : "d"(v)); return f;
}

// ------------------------------ main kernel ------------------------------
// CTA = (b, j-block of 8). 512 threads, 16 warps: wm = wid&3 (32 tile rows),
// wn = wid>>2 (32 n-cols = 16 l). Tile row r = il*8 + jl, i = ii*16+il, j = jb*8+jl.
// W smem: [n=2l+br (128)][kp halves (192 perm + pad)] rows of 212 halves (106 words).
// ks 0..3 = We (W rows 128..191), ks 4..7 = Wj (64..127), ks 8..11 = Wi (0..63).
#define WROWH   212
#define OFF_W   0                   // 128*424 = 54272
#define OFF_E16 54272               // 2 x 20480 = 40960
#define E16BUF  20480
#define OFF_PI  95232               // 128 x 66 float2 = 67584
#define PIW     66
#define OFF_PJ  162816              // 8 x 66 float2 = 4224
#define PJW     66
#define OFF_A   167040              // 128 i x 8 j fp32 = 4096
#define OFF_BS  171136              // 64 float2 (pre-halved) = 512
#define SMEM_DYN 171648

__global__ void __launch_bounds__(512, 1)
main_kernel(const float* __restrict__ A,
            const float* __restrict__ E,
            const float* __restrict__ H,
            const float* __restrict__ Watt,
            const float* __restrict__ Wnei,
            const float* __restrict__ biasA,
            const float* __restrict__ biasN,
            float* __restrict__ out) {
    extern __shared__ char sm[];
    const uint32_t sb = smem_u32(sm);

    const int t = threadIdx.x, lane = t & 31, wid = t >> 5;
    const int g = lane >> 2, tg = lane & 3;
    const int b = blockIdx.x >> 4, jb = blockIdx.x & 15;
    const int wm = wid & 3, wn = wid >> 2;
    const int mbase = wm * 32;

    const uint32_t* __restrict__ Ws = (const uint32_t*)(sm + OFF_W);

    // ---- A chunk via cp.async ----
    if (t < 256) {
        const int ia = t >> 1, ha = t & 1;
        cp16(sb + OFF_A + ia * 32 + ha * 16,
             (const char*)(A + ((size_t)(b * Nv + ia)) * Nv + jb * 8) + ha * 16);
        cp_commit();
    }

    // ---- W gather: coalesced fp32 LDG -> permuted fp16 STS (inline wprep) ----
    {
        unsigned short* __restrict__ Wh = (unsigned short*)(sm + OFF_W);
        #pragma unroll
        for (int v = 0; v < 12; v++) {
            const int gid4 = v * 512 + t;            // < 6144
            const int br = gid4 / 3072, rem = gid4 % 3072;
            const int row = rem >> 4, l4 = (rem & 15) * 4;
            const float* __restrict__ W = br ? Wnei : Watt;
            const float4 w4 = __ldg((const float4*)(W + row * 64 + l4));
            int ks;
            if (row >= 128)     ks = (row - 128) >> 4;
            else if (row >= 64) ks = row >> 4;
            else                ks = 8 + (row >> 4);
            const int k16 = row & 15;
            const int p16 = ((k16 >> 2) & 1) * 8 + ((k16 >> 1) & 1) * 4
                          + ((k16 >> 3) & 1) * 2 + (k16 & 1);
            const int kp = ks * 16 + p16;
            const float wv[4] = {w4.x, w4.y, w4.z, w4.w};
            #pragma unroll
            for (int q = 0; q < 4; q++) {
                const int n = 2 * (l4 + q) + br;
                Wh[n * WROWH + kp] = __half_as_ushort(__float2half_rn(wv[q]));
            }
        }
    }

    // ---- H tile: LDG -> fp16 permuted STS into E16 buf0 ----
    {
        const float4* Hg = (const float4*)(H + (size_t)b * Nv * FNv);
        float4 hl[4];
        #pragma unroll
        for (int v = 0; v < 4; v++) hl[v] = Hg[v * 512 + t];
        uint32_t* Ebw = (uint32_t*)(sm + OFF_E16);
        #pragma unroll
        for (int v = 0; v < 4; v++) {
            const int n = v * 512 + t, row = n >> 4, kgf = n & 15;
            const int wbase = row * 40 + (kgf >> 2) * 8 + ((kgf & 1) * 4) + ((kgf >> 1) & 1);
            Ebw[wbase]     = packh2(hl[v].x, hl[v].y);
            Ebw[wbase + 2] = packh2(hl[v].z, hl[v].w);
        }
    }
    if (t < 64)
        ((float2*)(sm + OFF_BS))[t] =
            make_float2(0.5f * __ldg(biasA + t), 0.5f * __ldg(biasN + t));
    cp_wait<0>();
    __syncthreads();          // W + A + H-tile resident

    // ---- prologue GEMM: Pi (ks 8..11, all rows); Pj (ks 4..7, warp wm==jb>>2) ----
    {
        const uint32_t* __restrict__ Ew = (const uint32_t*)(sm + OFF_E16);
        float cpi[2][4][4];
        #pragma unroll
        for (int mt = 0; mt < 2; mt++)
            #pragma unroll
            for (int nt = 0; nt < 4; nt++)
                #pragma unroll
                for (int q = 0; q < 4; q++) cpi[mt][nt][q] = 0.f;

        uint32_t a[2][4];
        #pragma unroll
        for (int ks = 0; ks < 4; ks++) {
            #pragma unroll
            for (int mt = 0; mt < 2; mt++) {
                const int r = mbase + mt * 16 + g;
                const uint2 u0 = *(const uint2*)(Ew + r * 40 + ks * 8 + tg * 2);
                const uint2 u1 = *(const uint2*)(Ew + (r + 8) * 40 + ks * 8 + tg * 2);
                a[mt][0] = u0.x; a[mt][1] = u1.x; a[mt][2] = u0.y; a[mt][3] = u1.y;
            }
            #pragma unroll
            for (int nt = 0; nt < 4; nt++) {
                const int nr = (wn * 32 + nt * 8 + g) * 106;
                const uint2 bi = *(const uint2*)(Ws + nr + (ks + 8) * 8 + tg * 2);
                mma16(cpi[0][nt], a[0], bi.x, bi.y);
                mma16(cpi[1][nt], a[1], bi.x, bi.y);
            }
        }
        // scatter Pi (all 128 rows)
        float2* __restrict__ PIs = (float2*)(sm + OFF_PI);
        #pragma unroll
        for (int mt = 0; mt < 2; mt++) {
            const int r0 = mbase + mt * 16 + g;
            #pragma unroll
            for (int nt = 0; nt < 4; nt++) {
                const int l = wn * 16 + nt * 4 + tg;
                PIs[(size_t)r0 * PIW + l]       = make_float2(cpi[mt][nt][0], cpi[mt][nt][1]);
                PIs[(size_t)(r0 + 8) * PIW + l] = make_float2(cpi[mt][nt][2], cpi[mt][nt][3]);
            }
        }

        if (wm == (jb >> 2)) {
            float cpj[2][4][4];
            #pragma unroll
            for (int mt = 0; mt < 2; mt++)
                #pragma unroll
                for (int nt = 0; nt < 4; nt++)
                    #pragma unroll
                    for (int q = 0; q < 4; q++) cpj[mt][nt][q] = 0.f;
            #pragma unroll
            for (int ks = 0; ks < 4; ks++) {
                #pragma unroll
                for (int mt = 0; mt < 2; mt++) {
                    const int r = mbase + mt * 16 + g;
                    const uint2 u0 = *(const uint2*)(Ew + r * 40 + ks * 8 + tg * 2);
                    const uint2 u1 = *(const uint2*)(Ew + (r + 8) * 40 + ks * 8 + tg * 2);
                    a[mt][0] = u0.x; a[mt][1] = u1.x; a[mt][2] = u0.y; a[mt][3] = u1.y;
                }
                #pragma unroll
                for (int nt = 0; nt < 4; nt++) {
                    const int nr = (wn * 32 + nt * 8 + g) * 106;
                    const uint2 bj = *(const uint2*)(Ws + nr + (ks + 4) * 8 + tg * 2);
                    mma16(cpj[0][nt], a[0], bj.x, bj.y);
                    mma16(cpj[1][nt], a[1], bj.x, bj.y);
                }
            }
            const int mtv = (jb >> 1) & 1, hv = jb & 1;
            float2* __restrict__ PJs = (float2*)(sm + OFF_PJ);
            #pragma unroll
            for (int nt = 0; nt < 4; nt++) {
                const int l = wn * 16 + nt * 4 + tg;
                PJs[(size_t)g * PJW + l] =
                    make_float2(cpj[mtv][nt][hv * 2], cpj[mtv][nt][hv * 2 + 1]);
            }
        }
    }

    // ---- hoist B fragments (We, ks 0..3) ----
    uint2 Breg[4][4];
    #pragma unroll
    for (int ks = 0; ks < 4; ks++)
        #pragma unroll
        for (int nt = 0; nt < 4; nt++)
            Breg[ks][nt] = *(const uint2*)(Ws + (wn * 32 + nt * 8 + g) * 106 + ks * 8 + tg * 2);

    // ---- prefetch E tile 0 ----
    float4 el[4];
    {
        #pragma unroll
        for (int v = 0; v < 4; v++) {
            const int n = v * 512 + t, row = n >> 4, kgf = n & 15;
            el[v] = __ldg((const float4*)
                (E + (((size_t)(b * Nv + (row >> 3)) * Nv) + jb * 8 + (row & 7)) * FNv) + kgf);
        }
    }
    __syncthreads();          // Pi/Pj visible; H reads done -> buf0 reusable

    // ---- Pj into registers ----
    double pj2[4];
    {
        const double* __restrict__ PJd = (const double*)(sm + OFF_PJ);
        #pragma unroll
        for (int nt = 0; nt < 4; nt++)
            pj2[nt] = PJd[(size_t)g * PJW + wn * 16 + nt * 4 + tg];
    }

    float outacc[4];
    #pragma unroll
    for (int nt = 0; nt < 4; nt++) outacc[nt] = 0.f;

    for (int ii = 0; ii < 8; ii++) {
        // ---- convert + store tile ii ----
        {
            uint32_t* Ebw = (uint32_t*)(sm + OFF_E16 + (ii & 1) * E16BUF);
            #pragma unroll
            for (int v = 0; v < 4; v++) {
                const int n = v * 512 + t, row = n >> 4, kgf = n & 15;
                const int wbase = row * 40 + (kgf >> 2) * 8 + ((kgf & 1) * 4) + ((kgf >> 1) & 1);
                Ebw[wbase]     = packh2(el[v].x, el[v].y);
                Ebw[wbase + 2] = packh2(el[v].z, el[v].w);
            }
        }
        __syncthreads();

        // ---- prefetch tile ii+1 ----
        if (ii + 1 < 8) {
            #pragma unroll
            for (int v = 0; v < 4; v++) {
                const int n = v * 512 + t, row = n >> 4, kgf = n & 15;
                el[v] = __ldg((const float4*)
                    (E + (((size_t)(b * Nv + (ii + 1) * 16 + (row >> 3)) * Nv)
                          + jb * 8 + (row & 7)) * FNv) + kgf);
            }
        }

        // ---- GEMM ----
        const uint32_t* __restrict__ Ew = (const uint32_t*)(sm + OFF_E16 + (ii & 1) * E16BUF);
        float c[2][4][4];
        #pragma unroll
        for (int mt = 0; mt < 2; mt++)
            #pragma unroll
            for (int nt = 0; nt < 4; nt++)
                #pragma unroll
                for (int q = 0; q < 4; q++) c[mt][nt][q] = 0.f;

        #pragma unroll
        for (int ks = 0; ks < 4; ks++) {
            uint32_t a[2][4];
            #pragma unroll
            for (int mt = 0; mt < 2; mt++) {
                const int r = mbase + mt * 16 + g;
                const uint2 u0 = *(const uint2*)(Ew + r * 40 + ks * 8 + tg * 2);
                const uint2 u1 = *(const uint2*)(Ew + (r + 8) * 40 + ks * 8 + tg * 2);
                a[mt][0] = u0.x; a[mt][1] = u1.x; a[mt][2] = u0.y; a[mt][3] = u1.y;
            }
            #pragma unroll
            for (int nt = 0; nt < 4; nt++) {
                mma16(c[0][nt], a[0], Breg[ks][nt].x, Breg[ks][nt].y);
                mma16(c[1][nt], a[1], Breg[ks][nt].x, Breg[ks][nt].y);
            }
        }

        // ---- epilogue: gate + i-accumulate ----
        const float*  __restrict__ As  = (const float*)(sm + OFF_A);
        const double* __restrict__ Pid = (const double*)(sm + OFF_PI);
        const double* __restrict__ Bsd = (const double*)(sm + OFF_BS);

        #pragma unroll
        for (int mt = 0; mt < 2; mt++) {
            #pragma unroll
            for (int h = 0; h < 2; h++) {
                const int i  = ii * 16 + wm * 4 + mt * 2 + h;
                const float ah = 0.5f * As[i * 8 + g];
                const double a2 = pack2d(ah, ah);
                const double* pir = Pid + (size_t)i * PIW;
                #pragma unroll
                for (int nt = 0; nt < 4; nt++) {
                    const int l = wn * 16 + nt * 4 + tg;
                    const double d2 = pack2d(c[mt][nt][h * 2], c[mt][nt][h * 2 + 1]);
                    const double s2 = add2(add2(d2, pir[l]), pj2[nt]);
                    const float2 r  = unpack2d(fma2v(a2, s2, Bsd[l]));
                    float th; asm("tanh.approx.f32 %0, %1;" : "=f"(th) : "f"(r.x));
                    outacc[nt] = fmaf(fmaxf(r.y, 0.f), fmaf(0.5f, th, 0.5f), outacc[nt]);
                }
            }
        }
    }

    // ---- cross-warp (wm) reduction + store ----
    __syncthreads();
    float* __restrict__ Sred = (float*)(sm + OFF_E16);   // [wm][wn][g][16] = 2048 floats
    #pragma unroll
    for (int nt = 0; nt < 4; nt++)
        Sred[((wm * 4 + wn) * 8 + g) * 16 + nt * 4 + tg] = outacc[nt];
    __syncthreads();

    {
        const int j = t >> 6, l = t & 63;
        const int wnn = l >> 4, lloc = l & 15;
        float s = 0.f;
        #pragma unroll
        for (int w = 0; w < 4; w++)
            s += Sred[((w * 4 + wnn) * 8 + j) * 16 + lloc];
        out[((size_t)(b * Nv) + jb * 8 + j) * FNv + l] = 2.f * s;   // undo pre-halving
    }
}

// ------------------------------ launch ------------------------------
extern "C" void kernel_launch(void* const* d_in, const int* in_sizes, int n_in,
                              void* d_out, int out_size) {
    const float* H    = (const float*)d_in[0];
    const float* A    = (const float*)d_in[1];
    const float* E    = (const float*)d_in[2];
    const float* Watt = (const float*)d_in[3];
    const float* Wnei = (const float*)d_in[4];
    const float* bAtt = (const float*)d_in[5];
    const float* bNei = (const float*)d_in[6];
    float* out = (float*)d_out;

    cudaFuncSetAttribute(main_kernel, cudaFuncAttributeMaxDynamicSharedMemorySize, SMEM_DYN);

    main_kernel<<<Bv * 16, 512, SMEM_DYN>>>(A, E, H, Watt, Wnei, bAtt, bNei, out);
}